// round 1
// baseline (speedup 1.0000x reference)
#include <cuda_runtime.h>
#include <cuda_bf16.h>

// PrecisionFocusedLoss: mean over B of ce(logits, t) * (1 + 3*penalty(t, argmax))
// C = 2, so:
//   u  = x1 - x0
//   ce = softplus(t ? -u : u)          (= -log_softmax[target])
//   w  = 1 + 3*penalty:
//        t=0: u>0 -> 16        (false positive, penalty 5)
//             u<=0 -> 1.3      (true negative, penalty 0.1)
//        t=1: u>0 -> 1.3       (true positive, penalty 0.1)
//             u<=0 -> 4        (false negative, penalty 1)
// argmax tie (u == 0) -> pred = 0 (jnp.argmax returns first max), handled by strict u > 0.

#define NBLOCKS 1024
#define NTHREADS 256

__device__ double g_partials[NBLOCKS];

// 1 + 3.0f * 0.1f in float arithmetic (match reference rounding exactly)
#define W_LOW  1.3000000119209290f
#define W_FN   4.0f
#define W_FP   16.0f

__device__ __forceinline__ float sample_loss(float x0, float x1, int t) {
    float u = x1 - x0;
    // z = (t==1) ? -u : u  ; ce = softplus(z)
    float z = t ? -u : u;
    float e = __expf(-fabsf(z));
    float ce = fmaxf(z, 0.0f) + __logf(1.0f + e);
    float w;
    if (t) w = (u > 0.0f) ? W_LOW : W_FN;
    else   w = (u > 0.0f) ? W_FP  : W_LOW;
    return ce * w;
}

__global__ void __launch_bounds__(NTHREADS)
loss_main(const float4* __restrict__ l4, const int4* __restrict__ t4,
          int nq, const float* __restrict__ logits,
          const int* __restrict__ targets, int n) {
    float acc = 0.0f;
    const int stride = gridDim.x * blockDim.x;
    for (int q = blockIdx.x * blockDim.x + threadIdx.x; q < nq; q += stride) {
        // 4 samples per iteration: 2 x float4 logits, 1 x int4 targets
        float4 L0 = l4[2 * q];
        float4 L1 = l4[2 * q + 1];
        int4   T  = t4[q];
        acc += sample_loss(L0.x, L0.y, T.x);
        acc += sample_loss(L0.z, L0.w, T.y);
        acc += sample_loss(L1.x, L1.y, T.z);
        acc += sample_loss(L1.z, L1.w, T.w);
    }
    // Tail (n not divisible by 4) — handled by one thread, added before reduce.
    if (blockIdx.x == 0 && threadIdx.x == 0) {
        for (int i = nq * 4; i < n; i++)
            acc += sample_loss(logits[2 * i], logits[2 * i + 1], targets[i]);
    }

    // Block reduction: warp shuffle, then cross-warp via shared.
    __shared__ float warp_sums[NTHREADS / 32];
    #pragma unroll
    for (int o = 16; o > 0; o >>= 1)
        acc += __shfl_down_sync(0xffffffffu, acc, o);
    if ((threadIdx.x & 31) == 0)
        warp_sums[threadIdx.x >> 5] = acc;
    __syncthreads();
    if (threadIdx.x < 32) {
        float v = (threadIdx.x < NTHREADS / 32) ? warp_sums[threadIdx.x] : 0.0f;
        #pragma unroll
        for (int o = (NTHREADS / 32) / 2; o > 0; o >>= 1)
            v += __shfl_down_sync(0xffffffffu, v, o);
        if (threadIdx.x == 0)
            g_partials[blockIdx.x] = (double)v;
    }
}

__global__ void __launch_bounds__(NBLOCKS)
loss_final(float* __restrict__ out, int n) {
    __shared__ double smem[NBLOCKS / 32];
    double v = g_partials[threadIdx.x];
    #pragma unroll
    for (int o = 16; o > 0; o >>= 1)
        v += __shfl_down_sync(0xffffffffu, v, o);
    if ((threadIdx.x & 31) == 0)
        smem[threadIdx.x >> 5] = v;
    __syncthreads();
    if (threadIdx.x < 32) {
        double s = (threadIdx.x < NBLOCKS / 32) ? smem[threadIdx.x] : 0.0;
        #pragma unroll
        for (int o = (NBLOCKS / 32) / 2; o > 0; o >>= 1)
            s += __shfl_down_sync(0xffffffffu, s, o);
        if (threadIdx.x == 0)
            out[0] = (float)(s / (double)n);
    }
}

extern "C" void kernel_launch(void* const* d_in, const int* in_sizes, int n_in,
                              void* d_out, int out_size) {
    const float* logits  = (const float*)d_in[0];   // (B, 2) f32
    const int*   targets = (const int*)d_in[1];     // (B,)   i32
    const int    n  = in_sizes[1];                  // B
    const int    nq = n >> 2;                       // quads of 4 samples

    loss_main<<<NBLOCKS, NTHREADS>>>(
        (const float4*)logits, (const int4*)targets, nq, logits, targets, n);
    loss_final<<<1, NBLOCKS>>>((float*)d_out, n);
}

// round 2
// speedup vs baseline: 1.1577x; 1.1577x over previous
#include <cuda_runtime.h>
#include <cuda_bf16.h>

// PrecisionFocusedLoss: mean over B of ce(logits, t) * (1 + 3*penalty(t, argmax))
// C = 2:
//   u  = x1 - x0
//   ce = softplus(t ? -u : u)
//   w  : t=0: u>0 -> 16 (FP), else 1.3 ; t=1: u>0 -> 1.3, else 4 (FN)
// argmax tie (u == 0) -> pred = 0, handled by strict u > 0.
//
// Single kernel: per-block double partials + last-block-finalizes pattern.
// Deterministic: finalize sums partials in fixed index order; counter is
// reset to 0 by the finalizing block, so graph replays are identical.

#define NBLOCKS 1024
#define NTHREADS 256

__device__ double g_partials[NBLOCKS];
__device__ unsigned int g_done_count;   // zero-init at load; reset after each use

#define W_LOW  1.3000000119209290f
#define W_FN   4.0f
#define W_FP   16.0f

__device__ __forceinline__ float sample_loss(float x0, float x1, int t) {
    float u = x1 - x0;
    float z = t ? -u : u;
    float e = __expf(-fabsf(z));
    float ce = fmaxf(z, 0.0f) + __logf(1.0f + e);
    float w;
    if (t) w = (u > 0.0f) ? W_LOW : W_FN;
    else   w = (u > 0.0f) ? W_FP  : W_LOW;
    return ce * w;
}

__global__ void __launch_bounds__(NTHREADS)
loss_fused(const float4* __restrict__ l4, const int4* __restrict__ t4,
           int nq, const float* __restrict__ logits,
           const int* __restrict__ targets, int n, float* __restrict__ out) {
    float acc = 0.0f;
    const int stride = gridDim.x * blockDim.x;
    for (int q = blockIdx.x * blockDim.x + threadIdx.x; q < nq; q += stride) {
        float4 L0 = l4[2 * q];
        float4 L1 = l4[2 * q + 1];
        int4   T  = t4[q];
        acc += sample_loss(L0.x, L0.y, T.x);
        acc += sample_loss(L0.z, L0.w, T.y);
        acc += sample_loss(L1.x, L1.y, T.z);
        acc += sample_loss(L1.z, L1.w, T.w);
    }
    // Tail (n % 4 != 0) — one thread handles it before the reduce.
    if (blockIdx.x == 0 && threadIdx.x == 0) {
        for (int i = nq * 4; i < n; i++)
            acc += sample_loss(logits[2 * i], logits[2 * i + 1], targets[i]);
    }

    // ── Block reduction ──
    __shared__ float warp_sums[NTHREADS / 32];
    #pragma unroll
    for (int o = 16; o > 0; o >>= 1)
        acc += __shfl_down_sync(0xffffffffu, acc, o);
    if ((threadIdx.x & 31) == 0)
        warp_sums[threadIdx.x >> 5] = acc;
    __syncthreads();

    __shared__ bool is_last;
    if (threadIdx.x == 0) {
        float v = 0.0f;
        #pragma unroll
        for (int i = 0; i < NTHREADS / 32; i++) v += warp_sums[i];
        g_partials[blockIdx.x] = (double)v;
        __threadfence();                       // partial visible before counter bump
        unsigned int c = atomicAdd(&g_done_count, 1u);
        is_last = (c == gridDim.x - 1);
    }
    __syncthreads();

    // ── Last block finalizes (deterministic fixed-order sum) ──
    if (is_last) {
        __shared__ double dsum[NTHREADS / 32];
        double v = 0.0;
        #pragma unroll
        for (int i = threadIdx.x; i < NBLOCKS; i += NTHREADS)
            v += g_partials[i];
        #pragma unroll
        for (int o = 16; o > 0; o >>= 1)
            v += __shfl_down_sync(0xffffffffu, v, o);
        if ((threadIdx.x & 31) == 0)
            dsum[threadIdx.x >> 5] = v;
        __syncthreads();
        if (threadIdx.x < 32) {
            double s = (threadIdx.x < NTHREADS / 32) ? dsum[threadIdx.x] : 0.0;
            #pragma unroll
            for (int o = (NTHREADS / 32) / 2; o > 0; o >>= 1)
                s += __shfl_down_sync(0xffffffffu, s, o);
            if (threadIdx.x == 0) {
                out[0] = (float)(s / (double)n);
                g_done_count = 0;              // reset for next graph replay
            }
        }
    }
}

extern "C" void kernel_launch(void* const* d_in, const int* in_sizes, int n_in,
                              void* d_out, int out_size) {
    const float* logits  = (const float*)d_in[0];   // (B, 2) f32
    const int*   targets = (const int*)d_in[1];     // (B,)   i32
    const int    n  = in_sizes[1];
    const int    nq = n >> 2;

    loss_fused<<<NBLOCKS, NTHREADS>>>(
        (const float4*)logits, (const int4*)targets, nq, logits, targets, n,
        (float*)d_out);
}